// round 15
// baseline (speedup 1.0000x reference)
#include <cuda_runtime.h>
#include <cstdint>

#define NPTS   16384
#define NPOINT 1024
#define NBATCH 4
#define NTHR   512
#define NWARP  16
#define CHUNKS 8                 // float4 chunks per thread (4 pts each)
#define PPT    32                // points per thread

// ---- packed f32x2 helpers (per-lane bit-identical to scalar rn ops) ----
#define PACK2(out, lo, hi) \
    asm("mov.b64 %0, {%1, %2};" : "=l"(out) : "f"(lo), "f"(hi))
#define UNPACK2(lo, hi, in) \
    asm("mov.b64 {%0, %1}, %2;" : "=f"(lo), "=f"(hi) : "l"(in))
#define ADD2(out, a, b) \
    asm("add.rn.f32x2 %0, %1, %2;" : "=l"(out) : "l"(a), "l"(b))
#define MUL2(out, a, b) \
    asm("mul.rn.f32x2 %0, %1, %2;" : "=l"(out) : "l"(a), "l"(b))
#define FMA2(out, a, b, c) \
    asm("fma.rn.f32x2 %0, %1, %2, %3;" : "=l"(out) : "l"(a), "l"(b), "l"(c))

// ---------------------------------------------------------------------------
// Fused FPS + ball query. One CTA (512 thr) per batch. xyz layout [B,3,N].
// Little-endian: a float4 (a,b,c,d) viewed as ulonglong2 gives packed pairs
// {lo=a,hi=b},{lo=c,hi=d} directly — zero-cost packing from LDG.128.
// Distance core packed f32x2 with the exact validated per-lane order
// (t=dx*dx; t=fma(dy,dy,t); t=fma(dz,dz,t)); min/update/max scalar.
// Per-warp lazy index find BEFORE the single barrier:
//   wmax = warp REDUX max; matching lanes scan dists for bit-equality
//   (descending => first occurrence); warp REDUX min => candidate.
// Block stage after ONE barrier: vmax = max(wmax), far = min candidate among
// warps with wmax == vmax — exact jnp.argmax semantics. Float32 output.
// ---------------------------------------------------------------------------
__global__ void __launch_bounds__(NTHR, 1)
fps_kernel(const float* __restrict__ xyz, float* __restrict__ out) {
    __shared__ unsigned s_v[2][NWARP];
    __shared__ unsigned s_i[2][NWARP];
    __shared__ int s_cent[NPOINT];

    const int tid  = threadIdx.x;
    const int warp = tid >> 5;
    const int lane = tid & 31;
    const int b    = blockIdx.x;

    const float* __restrict__ base = xyz + (size_t)b * 3 * NPTS;
    const float4* __restrict__ X4 = (const float4*)base;
    const float4* __restrict__ Y4 = X4 + NPTS / 4;
    const ulonglong2* __restrict__ Zu2 =
        (const ulonglong2*)(base + 2 * NPTS);

    // ---- load x,y packed (pairs straight from float4 bits); x-argmax ----
    unsigned long long ux[2 * CHUNKS], uy[2 * CHUNKS];
    float dist[PPT];
    float mv0 = -1.0f; int mi0 = 0;
    #pragma unroll
    for (int c = 0; c < CHUNKS; c++) {
        const float4 X = __ldg(&X4[c * NTHR + tid]);
        const float4 Y = __ldg(&Y4[c * NTHR + tid]);
        PACK2(ux[2*c],     X.x, X.y);
        PACK2(ux[2*c + 1], X.z, X.w);
        PACK2(uy[2*c],     Y.x, Y.y);
        PACK2(uy[2*c + 1], Y.z, Y.w);
        const int p = (c * NTHR + tid) * 4;
        if (X.x > mv0) { mv0 = X.x; mi0 = p;     }
        if (X.y > mv0) { mv0 = X.y; mi0 = p + 1; }
        if (X.z > mv0) { mv0 = X.z; mi0 = p + 2; }
        if (X.w > mv0) { mv0 = X.w; mi0 = p + 3; }
    }
    #pragma unroll
    for (int i = 0; i < PPT; i++) dist[i] = 1e10f;

    // ---- initial block argmax over x (value+index, one-time) ----
    int far;
    {
        const unsigned vb   = __float_as_uint(mv0);
        const unsigned wmax = __reduce_max_sync(0xffffffffu, vb);
        const unsigned cand = (vb == wmax) ? (unsigned)mi0 : 0xFFFFFFFFu;
        const unsigned imin = __reduce_min_sync(0xffffffffu, cand);
        if (lane == 0) { s_v[0][warp] = wmax; s_i[0][warp] = imin; }
        __syncthreads();
        const unsigned tv    = (lane < NWARP) ? s_v[0][lane] : 0u;
        const unsigned tvmax = __reduce_max_sync(0xffffffffu, tv);
        const unsigned tcand = (lane < NWARP && tv == tvmax) ? s_i[0][lane]
                                                             : 0xFFFFFFFFu;
        far = (int)__reduce_min_sync(0xffffffffu, tcand);
        __syncthreads();   // isolate initial buffer use from loop step 0
    }

    // ---- FPS main loop (ONE barrier per step) ----
    for (int k = 0; k < NPOINT; k++) {
        if (tid == 0) s_cent[k] = far;

        const float cx = __ldg(&base[far]);
        const float cy = __ldg(&base[NPTS + far]);
        const float cz = __ldg(&base[2 * NPTS + far]);
        unsigned long long ncxx, ncyy, nczz;
        PACK2(ncxx, -cx, -cx);
        PACK2(ncyy, -cy, -cy);
        PACK2(nczz, -cz, -cz);

        float mvA = -1.0f, mvB = -1.0f;
        #pragma unroll
        for (int c = 0; c < CHUNKS; c++) {
            const ulonglong2 Zu = __ldg(&Zu2[c * NTHR + tid]);
            #pragma unroll
            for (int j = 0; j < 2; j++) {
                unsigned long long dx2, dy2, dz2, t2;
                ADD2(dx2, ux[2*c + j], ncxx);   // fadd(v,-c) == fsub(v,c)
                ADD2(dy2, uy[2*c + j], ncyy);
                ADD2(dz2, (j ? Zu.y : Zu.x), nczz);
                MUL2(t2, dx2, dx2);
                FMA2(t2, dy2, dy2, t2);         // dy*dy + dx*dx
                FMA2(t2, dz2, dz2, t2);         // dz*dz + (...)  exact order
                float t0, t1;
                UNPACK2(t0, t1, t2);
                const int i0 = c * 4 + 2*j;
                const float dd0 = fminf(dist[i0],     t0);
                const float dd1 = fminf(dist[i0 + 1], t1);
                dist[i0]     = dd0;
                dist[i0 + 1] = dd1;
                mvA = fmaxf(mvA, dd0);
                mvB = fmaxf(mvB, dd1);
            }
        }
        const float mv = fmaxf(mvA, mvB);

        // ---- warp stage: value max + lazy first-occurrence candidate ----
        const unsigned vb   = __float_as_uint(mv);       // all >= 0
        const unsigned wmax = __reduce_max_sync(0xffffffffu, vb);
        unsigned p = 0xFFFFFFFFu;
        if (vb == wmax) {                 // only possible if own max == wmax
            #pragma unroll
            for (int i = PPT - 1; i >= 0; i--) {   // descending => first occ.
                if (__float_as_uint(dist[i]) == wmax)
                    p = (unsigned)(((i >> 2) * NTHR + tid) * 4 + (i & 3));
            }
        }
        const unsigned pw = __reduce_min_sync(0xffffffffu, p);
        const int par = k & 1;
        if (lane == 0) { s_v[par][warp] = wmax; s_i[par][warp] = pw; }
        __syncthreads();                                  // the ONE barrier

        // ---- block stage (every warp, redundant, no extra barrier) ----
        const unsigned tv   = (lane < NWARP) ? s_v[par][lane] : 0u;
        const unsigned vmax = __reduce_max_sync(0xffffffffu, tv);
        const unsigned ti   = (lane < NWARP && tv == vmax) ? s_i[par][lane]
                                                           : 0xFFFFFFFFu;
        far = (int)__reduce_min_sync(0xffffffffu, ti);
    }
    __syncthreads();   // s_cent complete

    // ---- ball query: 16 warps, 64 centroids each ----
    for (int s = warp; s < NPOINT; s += NWARP) {
        const int c = s_cent[s];
        const float xs = __ldg(&base[c]);
        const float ys = __ldg(&base[NPTS + c]);
        const float zs = __ldg(&base[2 * NPTS + c]);
        const float snorm = __fmaf_rn(zs, zs,
                            __fmaf_rn(ys, ys, __fmul_rn(xs, xs)));

        int winner = NPTS;
        for (int j0 = 0; j0 < NPTS; j0 += 32) {
            const int j = j0 + lane;
            const float xj = __ldg(&base[j]);
            const float yj = __ldg(&base[NPTS + j]);
            const float zj = __ldg(&base[2 * NPTS + j]);
            const float dot   = __fmaf_rn(zs, zj,
                                __fmaf_rn(ys, yj, __fmul_rn(xs, xj)));
            const float dnorm = __fmaf_rn(zj, zj,
                                __fmaf_rn(yj, yj, __fmul_rn(xj, xj)));
            const float d = __fadd_rn(__fmaf_rn(-2.0f, dot, snorm), dnorm);
            const unsigned m = __ballot_sync(0xffffffffu, !(d > 0.25f));
            if (m) { winner = j0 + __ffs(m) - 1; break; }
        }
        if (lane == 0) out[b * NPOINT + s] = (float)winner;
    }
}

// ---------------------------------------------------------------------------
extern "C" void kernel_launch(void* const* d_in, const int* in_sizes, int n_in,
                              void* d_out, int out_size) {
    int xi = 0;
    for (int i = 0; i < n_in; i++) {
        if (in_sizes[i] == NBATCH * 3 * NPTS) { xi = i; break; }
    }
    const float* xyz = (const float*)d_in[xi];
    float* out = (float*)d_out;

    fps_kernel<<<NBATCH, NTHR>>>(xyz, out);
}